// round 7
// baseline (speedup 1.0000x reference)
#include <cuda_runtime.h>

#define NT 512
#define BT 8

typedef unsigned long long u64;

// ---------------- packed f32x2 helpers ----------------
__device__ __forceinline__ void ffma2(u64 &acc, u64 a, u64 w) {
    asm("fma.rn.f32x2 %0, %1, %2, %0;" : "+l"(acc) : "l"(a), "l"(w));
}
__device__ __forceinline__ float sum2(u64 v) {
    return __uint_as_float((unsigned int)v) + __uint_as_float((unsigned int)(v >> 32));
}

// ---------------- activations ----------------
__device__ __forceinline__ float softplus_f(float x) {
    float r = __logf(1.f + __expf(x));
    return (x > 15.f) ? x : r;
}
__device__ __forceinline__ float tanh_f(float x) {
    float xx = fminf(fmaxf(x, -12.f), 12.f);
    float e = __expf(2.f * xx);
    return (e - 1.f) * __fdividef(1.f, e + 1.f);
}

// ---------------- slice-interleaved weight layout ----------------
// For a [C x K] row-major weight matrix, lane s (0..7) owns k-slice
// [s*K/8, (s+1)*K/8). Layout: dst[c*K + i*32 + s*4 + j] = src[c*K + k]
// where k = s*(K/8) + i*4 + j. A warp load at (c*K + i*32 + s*4) with the
// 8 s-values is 128B contiguous -> 1 wavefront, conflict-free.
__device__ float g_w3L[512 * 128];
__device__ float g_w1L[128 * 64];
__device__ float g_w2L[128 * 128];
__device__ float g_i2L[128 * 128];
__device__ float g_i3L[64 * 128];

__device__ __forceinline__ void prep_one(float* dst, const float* src, int K, int id) {
    int c = id / K, k = id % K;
    int ss = K / 8;
    int s = k / ss, rem = k % ss, i = rem >> 2, j = rem & 3;
    dst[c * K + i * 32 + s * 4 + j] = src[id];
}

__global__ void prep_all(const float* __restrict__ vw3, const float* __restrict__ vw1,
                         const float* __restrict__ vw2, const float* __restrict__ iw2,
                         const float* __restrict__ iw3) {
    int id = blockIdx.x * blockDim.x + threadIdx.x;
    if (id < 65536) { prep_one(g_w3L, vw3, 128, id); return; }
    id -= 65536;
    if (id < 8192)  { prep_one(g_w1L, vw1, 64, id); return; }
    id -= 8192;
    if (id < 16384) { prep_one(g_w2L, vw2, 128, id); return; }
    id -= 16384;
    if (id < 16384) { prep_one(g_i2L, iw2, 128, id); return; }
    id -= 16384;
    if (id < 8192)  { prep_one(g_i3L, iw3, 128, id); return; }
}

// ---------------- smem layout (floats) ----------------
#define OFF_W1  0          // 8192  (vw1 slice-interleaved)
#define OFF_W2  8192       // 16384 (vw2 slice-interleaved)
#define OFF_W3S 24576      // 16384 (vw3 cols 384..511 slice-interleaved)
#define OFF_B1  40960      // 128
#define OFF_B2  41088      // 128
#define OFF_B3  41216      // 512
#define OFF_LW  41728      // 64
#define OFF_DX  41792      // 64
#define OFF_Y   41856      // 8 x 68
#define OFF_YT  42400      // 8 x 68
#define OFF_H1  42944      // 8 x 132
#define OFF_H2  44000      // 8 x 132
#define OFF_K   45056      // 6 x 8 x 68
#define SMEM_FLOATS 48320
#define SMEM_BYTES (SMEM_FLOATS * 4)

enum { ACT_ID = 0, ACT_RELU = 1, ACT_SP = 2 };

// Warp-cooperative dense: OUT[8][C] = act( ACTS[8][K] @ W[C][K]^T + bias ).
// lane = rp*8+s: rows {2rp,2rp+1}, k-slice s. Acts preloaded to registers.
// Warp wid owns C/16 consecutive columns; weights read once per CTA.
template<int K, int C, int ACT>
__device__ __forceinline__ void warp_dense(const float* __restrict__ wL,
                                           const float* __restrict__ bias,
                                           const float* __restrict__ act, int as,
                                           float* __restrict__ outp, int os,
                                           int wid, int lane) {
    constexpr int CW = C / 16;
    constexpr int NI = K / 32;
    const int rp = lane >> 3, s = lane & 7;

    u64 a[2][2 * NI];
#pragma unroll
    for (int r2 = 0; r2 < 2; r2++) {
        const float* ab = act + (2 * rp + r2) * as + s * (K / 8);
#pragma unroll
        for (int i = 0; i < NI; i++) {
            ulonglong2 t = *(const ulonglong2*)(ab + i * 4);
            a[r2][2 * i] = t.x; a[r2][2 * i + 1] = t.y;
        }
    }

    const float* wb = wL + (wid * CW) * K + s * 4;
#pragma unroll
    for (int cc = 0; cc < CW; cc++) {
        u64 acc0 = 0ull, acc1 = 0ull;
        const float* wp = wb + cc * K;
#pragma unroll
        for (int i = 0; i < NI; i++) {
            ulonglong2 w = *(const ulonglong2*)(wp + i * 32);
            ffma2(acc0, a[0][2 * i],     w.x);
            ffma2(acc0, a[0][2 * i + 1], w.y);
            ffma2(acc1, a[1][2 * i],     w.x);
            ffma2(acc1, a[1][2 * i + 1], w.y);
        }
        float v0 = sum2(acc0), v1 = sum2(acc1);
        v0 += __shfl_xor_sync(0xffffffffu, v0, 1);
        v1 += __shfl_xor_sync(0xffffffffu, v1, 1);
        v0 += __shfl_xor_sync(0xffffffffu, v0, 2);
        v1 += __shfl_xor_sync(0xffffffffu, v1, 2);
        v0 += __shfl_xor_sync(0xffffffffu, v0, 4);
        v1 += __shfl_xor_sync(0xffffffffu, v1, 4);
        if (s < 2) {
            int c = wid * CW + cc;
            float v = (s ? v1 : v0) + bias[c];
            if (ACT == ACT_RELU) v = fmaxf(v, 0.f);
            if (ACT == ACT_SP)   v = softplus_f(v);
            outp[(2 * rp + s) * os + c] = v;
        }
    }
}

// L3 inner: warp covers cols [c0, c0+32) with weight base wq (layout col*128),
// computes tanh(v+b3)*dx and accumulates kout[8][4 h-cols] in registers.
__device__ __forceinline__ void l3_inner(const float* __restrict__ wq,
                                         const float* __restrict__ h2s,
                                         const float* __restrict__ b3s,
                                         const float* __restrict__ dxs,
                                         float* __restrict__ kout,
                                         int c0, int lane) {
    const int rp = lane >> 3, s = lane & 7;

    u64 a[2][8];
#pragma unroll
    for (int r2 = 0; r2 < 2; r2++) {
        const float* ab = h2s + (2 * rp + r2) * 132 + s * 16;
#pragma unroll
        for (int i = 0; i < 4; i++) {
            ulonglong2 t = *(const ulonglong2*)(ab + i * 4);
            a[r2][2 * i] = t.x; a[r2][2 * i + 1] = t.y;
        }
    }

    float kacc[4] = {0.f, 0.f, 0.f, 0.f};
    const float* wb = wq + s * 4;
#pragma unroll 4
    for (int cc = 0; cc < 32; cc++) {
        u64 acc0 = 0ull, acc1 = 0ull;
        const float* wp = wb + cc * 128;
#pragma unroll
        for (int i = 0; i < 4; i++) {
            ulonglong2 w = *(const ulonglong2*)(wp + i * 32);
            ffma2(acc0, a[0][2 * i],     w.x);
            ffma2(acc0, a[0][2 * i + 1], w.y);
            ffma2(acc1, a[1][2 * i],     w.x);
            ffma2(acc1, a[1][2 * i + 1], w.y);
        }
        float v0 = sum2(acc0), v1 = sum2(acc1);
        v0 += __shfl_xor_sync(0xffffffffu, v0, 1);
        v1 += __shfl_xor_sync(0xffffffffu, v1, 1);
        v0 += __shfl_xor_sync(0xffffffffu, v0, 2);
        v1 += __shfl_xor_sync(0xffffffffu, v1, 2);
        v0 += __shfl_xor_sync(0xffffffffu, v0, 4);
        v1 += __shfl_xor_sync(0xffffffffu, v1, 4);
        if (s < 2) {
            int r = 2 * rp + s;
            int c = c0 + cc;
            float f = tanh_f((s ? v1 : v0) + b3s[c]);
            kacc[cc >> 3] += f * dxs[r * 8 + (cc & 7)];
        }
    }
    if (s < 2) {
        int r = 2 * rp + s;
#pragma unroll
        for (int hh = 0; hh < 4; hh++)
            kout[r * 68 + (c0 >> 3) + hh] = kacc[hh];
    }
}

__device__ __forceinline__ void vf(const float* __restrict__ ysrc, float* __restrict__ kout,
                                   const float* w1L, const float* b1s,
                                   const float* w2L, const float* b2s,
                                   const float* w3s, const float* b3s,
                                   const float* dxs,
                                   float* h1, float* h2, int wid, int lane) {
    warp_dense<64, 128, ACT_SP>(w1L, b1s, ysrc, 68, h1, 132, wid, lane);
    __syncthreads();
    warp_dense<128, 128, ACT_SP>(w2L, b2s, h1, 132, h2, 132, wid, lane);
    __syncthreads();
    if (wid < 12)
        l3_inner(g_w3L + (wid * 32) * 128, h2, b3s, dxs, kout, wid * 32, lane);
    else
        l3_inner(w3s + (wid * 32 - 384) * 128, h2, b3s, dxs, kout, wid * 32, lane);
    __syncthreads();
}

__device__ __forceinline__ void write_out(const float* __restrict__ y,
                                          const float* __restrict__ lws, float lbv,
                                          float* __restrict__ out, int b0, int t, int tid) {
    int w = tid >> 5, l = tid & 31;
    if (w < 8) {
        float p = y[w * 68 + l] * lws[l] + y[w * 68 + 32 + l] * lws[32 + l];
#pragma unroll
        for (int sft = 16; sft > 0; sft >>= 1) p += __shfl_xor_sync(0xffffffffu, p, sft);
        if (l == 0) {
            float z = p + lbv;
            out[(b0 + w) * 64 + t] = __fdividef(1.f, 1.f + __expf(-z));
        }
    }
}

__global__ void __launch_bounds__(NT, 1)
cde_kernel(const float* __restrict__ ts, const float* __restrict__ xs,
           const float* __restrict__ iw1, const float* __restrict__ ib1,
           const float* __restrict__ ib2, const float* __restrict__ ib3,
           const float* __restrict__ vb1, const float* __restrict__ vb2,
           const float* __restrict__ vb3,
           const float* __restrict__ lw, const float* __restrict__ lb,
           float* __restrict__ out) {
    extern __shared__ float sm[];
    const int tid = threadIdx.x;
    const int wid = tid >> 5, lane = tid & 31;
    const int b0 = blockIdx.x * BT;

    float* w1L = sm + OFF_W1;
    float* w2L = sm + OFF_W2;
    float* w3s = sm + OFF_W3S;
    float* b1s = sm + OFF_B1;
    float* b2s = sm + OFF_B2;
    float* b3s = sm + OFF_B3;
    float* lws = sm + OFF_LW;
    float* dxs = sm + OFF_DX;
    float* ybuf = sm + OFF_Y;
    float* yts = sm + OFF_YT;
    float* h1 = sm + OFF_H1;
    float* h2 = sm + OFF_H2;
    float* ksb = sm + OFF_K;

    // ---------- stage weights + misc into smem ----------
    for (int i = tid; i < 8192; i += NT)  w1L[i] = g_w1L[i];
    for (int i = tid; i < 16384; i += NT) w2L[i] = g_w2L[i];
    for (int i = tid; i < 16384; i += NT) w3s[i] = g_w3L[384 * 128 + i];
    for (int i = tid; i < 128; i += NT) { b1s[i] = vb1[i]; b2s[i] = vb2[i]; }
    for (int i = tid; i < 512; i += NT) b3s[i] = vb3[i];
    if (tid < 64) lws[tid] = lw[tid];
    if (tid < 64) {
        int r = tid >> 3, d = tid & 7;
        dxs[tid] = xs[(b0 + r) * 512 + d];        // X(t0)
    }
    const float lbv = lb[0];
    __syncthreads();

    // ---------- initial MLP ----------
    {   // layer 1 (K=8): simple per-thread
        int c = tid & 127, rg = tid >> 7;
#pragma unroll
        for (int r2 = 0; r2 < 2; r2++) {
            int r = rg * 2 + r2;
            float acc = ib1[c];
#pragma unroll
            for (int k = 0; k < 8; k++) acc += dxs[r * 8 + k] * iw1[c * 8 + k];
            h1[r * 132 + c] = fmaxf(acc, 0.f);
        }
    }
    __syncthreads();
    warp_dense<128, 128, ACT_RELU>(g_i2L, ib2, h1, 132, h2, 132, wid, lane);
    __syncthreads();
    warp_dense<128, 64, ACT_ID>(g_i3L, ib3, h2, 132, ybuf, 68, wid, lane);
    __syncthreads();

    write_out(ybuf, lws, lbv, out, b0, 0, tid);
    __syncthreads();

    // Tsit5 coefficients
    const float A21 = 0.161f;
    const float A31 = -0.008480655492356989f, A32 = 0.335480655492357f;
    const float A41 = 2.8971530571054935f, A42 = -6.359448489975075f, A43 = 4.3622954328695815f;
    const float A51 = 5.325864828439257f, A52 = -11.748883564062828f, A53 = 7.4955393428898365f, A54 = -0.09249506636175525f;
    const float A61 = 5.86145544294642f, A62 = -12.92096931784711f, A63 = 8.159367898576159f, A64 = -0.071584973281401f, A65 = -0.028269050394068383f;
    const float B1 = 0.09646076681806523f, B2 = 0.01f, B3 = 0.4798896504144996f;
    const float B4 = 1.379008574103742f, B5 = -3.290069515436081f, B6 = 2.324710524099774f;

    float* k1 = ksb;
    float* k2 = ksb + 544;
    float* k3 = ksb + 1088;
    float* k4 = ksb + 1632;
    float* k5 = ksb + 2176;
    float* k6 = ksb + 2720;

    const int er = (tid >> 6) * 68 + (tid & 63);   // padded index for this thread's element

    for (int t = 0; t < 63; t++) {
        const float dt = ts[t + 1] - ts[t];
        if (tid < 64) {
            int r = tid >> 3, d = tid & 7;
            int ix = (b0 + r) * 512 + t * 8 + d;
            dxs[tid] = (xs[ix + 8] - xs[ix]) / dt;
        }
        __syncthreads();

        // stage 1
        vf(ybuf, k1, w1L, b1s, w2L, b2s, w3s, b3s, dxs, h1, h2, wid, lane);
        yts[er] = ybuf[er] + dt * (A21 * k1[er]);
        __syncthreads();
        // stage 2
        vf(yts, k2, w1L, b1s, w2L, b2s, w3s, b3s, dxs, h1, h2, wid, lane);
        yts[er] = ybuf[er] + dt * (A31 * k1[er] + A32 * k2[er]);
        __syncthreads();
        // stage 3
        vf(yts, k3, w1L, b1s, w2L, b2s, w3s, b3s, dxs, h1, h2, wid, lane);
        yts[er] = ybuf[er] + dt * (A41 * k1[er] + A42 * k2[er] + A43 * k3[er]);
        __syncthreads();
        // stage 4
        vf(yts, k4, w1L, b1s, w2L, b2s, w3s, b3s, dxs, h1, h2, wid, lane);
        yts[er] = ybuf[er] + dt * (A51 * k1[er] + A52 * k2[er] + A53 * k3[er] + A54 * k4[er]);
        __syncthreads();
        // stage 5
        vf(yts, k5, w1L, b1s, w2L, b2s, w3s, b3s, dxs, h1, h2, wid, lane);
        yts[er] = ybuf[er] + dt * (A61 * k1[er] + A62 * k2[er] + A63 * k3[er] + A64 * k4[er] + A65 * k5[er]);
        __syncthreads();
        // stage 6
        vf(yts, k6, w1L, b1s, w2L, b2s, w3s, b3s, dxs, h1, h2, wid, lane);
        ybuf[er] = ybuf[er] + dt * (B1 * k1[er] + B2 * k2[er] + B3 * k3[er]
                                  + B4 * k4[er] + B5 * k5[er] + B6 * k6[er]);
        __syncthreads();
        write_out(ybuf, lws, lbv, out, b0, t + 1, tid);
        __syncthreads();
    }
}

extern "C" void kernel_launch(void* const* d_in, const int* in_sizes, int n_in,
                              void* d_out, int out_size) {
    const float* ts  = (const float*)d_in[0];
    const float* xs  = (const float*)d_in[1];
    const float* iw1 = (const float*)d_in[2];
    const float* ib1 = (const float*)d_in[3];
    const float* iw2 = (const float*)d_in[4];
    const float* ib2 = (const float*)d_in[5];
    const float* iw3 = (const float*)d_in[6];
    const float* ib3 = (const float*)d_in[7];
    const float* vw1 = (const float*)d_in[8];
    const float* vb1 = (const float*)d_in[9];
    const float* vw2 = (const float*)d_in[10];
    const float* vb2 = (const float*)d_in[11];
    const float* vw3 = (const float*)d_in[12];
    const float* vb3 = (const float*)d_in[13];
    const float* lw  = (const float*)d_in[14];
    const float* lb  = (const float*)d_in[15];
    float* out = (float*)d_out;

    prep_all<<<(114688 + 255) / 256, 256>>>(vw3, vw1, vw2, iw2, iw3);

    cudaFuncSetAttribute(cde_kernel, cudaFuncAttributeMaxDynamicSharedMemorySize, SMEM_BYTES);
    cde_kernel<<<128, NT, SMEM_BYTES>>>(ts, xs, iw1, ib1, ib2, ib3,
                                        vb1, vb2, vb3, lw, lb, out);
}

// round 9
// speedup vs baseline: 2.3865x; 2.3865x over previous
#include <cuda_runtime.h>

#define NT 512
#define BT 8

typedef unsigned long long u64;

// ---------------- packed f32x2 helpers ----------------
__device__ __forceinline__ void ffma2(u64 &acc, u64 a, u64 w) {
    asm("fma.rn.f32x2 %0, %1, %2, %0;" : "+l"(acc) : "l"(a), "l"(w));
}
__device__ __forceinline__ float sum2(u64 v) {
    return __uint_as_float((unsigned int)v) + __uint_as_float((unsigned int)(v >> 32));
}

// ---------------- activations ----------------
__device__ __forceinline__ float softplus_f(float x) {
    float r = __logf(1.f + __expf(x));
    return (x > 15.f) ? x : r;
}
__device__ __forceinline__ float tanh_f(float x) {
    float xx = fminf(fmaxf(x, -12.f), 12.f);
    float e = __expf(2.f * xx);
    return (e - 1.f) * __fdividef(1.f, e + 1.f);
}

// ---------------- k-major quad-interleaved weight layouts ----------------
// dst[(k>>2)*C*4 + c*4 + (k&3)] = src[c*K + k]
__device__ float g_vw3q[512 * 128];
__device__ float g_vw1k[128 * 64];
__device__ float g_vw2k[128 * 128];
__device__ float g_iw1k[128 * 8];
__device__ float g_iw2k[128 * 128];
__device__ float g_iw3k[64 * 128];

__global__ void prep_kmajor(float* __restrict__ dst, const float* __restrict__ src,
                            int C, int K) {
    int id = blockIdx.x * blockDim.x + threadIdx.x;
    if (id >= C * K) return;
    int c = id / K;
    int k = id % K;
    dst[(k >> 2) * C * 4 + c * 4 + (k & 3)] = src[id];
}

// ---------------- smem layout (floats) ----------------
#define OFF_W1  0          // vw1 k-major: 16 kq x 128 x 4 = 8192
#define OFF_W3C 8192       // vw3 cols 256..511: 32 kq x 256 x 4 = 32768
#define OFF_B1  40960      // 128
#define OFF_B2  41088      // 128
#define OFF_B3  41216      // 512
#define OFF_LW  41728      // 64
#define OFF_DX  41792      // 64
#define OFF_Y   41856      // 512
#define OFF_YT  42368      // 512
#define OFF_H1  42880      // 8 x 128
#define OFF_H2  43904      // 8 x 128
#define OFF_K   44928      // 6 x 512
#define OFF_SC  48000      // scratch 2 x 4096
#define SMEM_FLOATS 56192
#define SMEM_BYTES (SMEM_FLOATS * 4)

enum { ACT_ID = 0, ACT_RELU = 1, ACT_SP = 2 };

// Split-K dense with weights from SMEM/GMEM pointer (k-major quad-interleaved).
template<int C, int K, int ACT>
__device__ __forceinline__ void dense_sk(const float* __restrict__ wk,
                                         const float* __restrict__ bias,
                                         const float* __restrict__ actbuf,
                                         float* __restrict__ scratch,
                                         float* __restrict__ outp, int tid) {
    const int half = tid >> 8;
    const int t2 = tid & 255;
    constexpr int G = 256 / C;
    constexpr int RPT = 8 / G;
    constexpr int KQH = K / 8;
    const int c  = t2 % C;
    const int r0 = (t2 / C) * RPT;
    const int kq0 = half * KQH;

    u64 acc[RPT][2];
#pragma unroll
    for (int i = 0; i < RPT; i++) { acc[i][0] = 0ull; acc[i][1] = 0ull; }

#pragma unroll
    for (int q = 0; q < KQH; q++) {
        const int kq = kq0 + q;
        ulonglong2 w = *(const ulonglong2*)(wk + kq * C * 4 + c * 4);
#pragma unroll
        for (int i = 0; i < RPT; i++) {
            ulonglong2 a = *(const ulonglong2*)(actbuf + (r0 + i) * K + kq * 4);
            ffma2(acc[i][0], a.x, w.x);
            ffma2(acc[i][1], a.y, w.y);
        }
    }
#pragma unroll
    for (int i = 0; i < RPT; i++)
        scratch[half * (8 * C) + (r0 + i) * C + c] = sum2(acc[i][0]) + sum2(acc[i][1]);
    __syncthreads();

#pragma unroll
    for (int i = tid; i < 8 * C; i += NT) {
        float v = scratch[i] + scratch[8 * C + i] + bias[i % C];
        if (ACT == ACT_RELU) v = fmaxf(v, 0.f);
        if (ACT == ACT_SP)   v = softplus_f(v);
        outp[i] = v;
    }
}

// L2 dense (C=128, K=128) with REGISTER-RESIDENT weights (this thread's
// 16-kq slice of vw2, loaded once at kernel start). Zero weight smem traffic.
__device__ __forceinline__ void dense2_reg(const ulonglong2* __restrict__ w2r,
                                           const float* __restrict__ bias,
                                           const float* __restrict__ actbuf,
                                           float* __restrict__ scratch,
                                           float* __restrict__ outp, int tid) {
    const int half = tid >> 8;
    const int t2 = tid & 255;
    const int c  = t2 & 127;
    const int r0 = (t2 >> 7) * 4;
    const int kq0 = half * 16;

    u64 acc[4][2];
#pragma unroll
    for (int i = 0; i < 4; i++) { acc[i][0] = 0ull; acc[i][1] = 0ull; }

#pragma unroll
    for (int q = 0; q < 16; q++) {
        ulonglong2 w = w2r[q];
#pragma unroll
        for (int i = 0; i < 4; i++) {
            ulonglong2 a = *(const ulonglong2*)(actbuf + (r0 + i) * 128 + (kq0 + q) * 4);
            ffma2(acc[i][0], a.x, w.x);
            ffma2(acc[i][1], a.y, w.y);
        }
    }
#pragma unroll
    for (int i = 0; i < 4; i++)
        scratch[half * 1024 + (r0 + i) * 128 + c] = sum2(acc[i][0]) + sum2(acc[i][1]);
    __syncthreads();

#pragma unroll
    for (int i = tid; i < 1024; i += NT) {
        float v = scratch[i] + scratch[1024 + i] + bias[i & 127];
        outp[i] = softplus_f(v);
    }
}

// L3 (512 cols, K=128) split-K + tanh + dx-contraction -> kout[8][64].
// Col t2 streamed from L2 (depth-2 prefetch), col t2+256 from SMEM cache.
__device__ __forceinline__ void l3_sk(const float* __restrict__ h2s,
                                      const float* __restrict__ w3c,
                                      const float* __restrict__ b3s,
                                      const float* __restrict__ dxs,
                                      float* __restrict__ scratch,
                                      float* __restrict__ kout, int tid) {
    const int half = tid >> 8;
    const int t2 = tid & 255;

    u64 acc0[8], acc1[8];
#pragma unroll
    for (int r = 0; r < 8; r++) { acc0[r] = 0ull; acc1[r] = 0ull; }

    const float* gb = g_vw3q + (half * 16) * 2048 + t2 * 4;
    const float* cb = w3c + (half * 16) * 1024 + t2 * 4;
    ulonglong2 p0 = *(const ulonglong2*)(gb);
    ulonglong2 p1 = *(const ulonglong2*)(gb + 2048);

#pragma unroll
    for (int q = 0; q < 16; q++) {
        ulonglong2 w0 = p0;
        p0 = p1;
        if (q + 2 < 16) p1 = *(const ulonglong2*)(gb + (q + 2) * 2048);
        ulonglong2 w1 = *(const ulonglong2*)(cb + q * 1024);
        const int k4 = (half * 16 + q) * 4;
#pragma unroll
        for (int r = 0; r < 8; r++) {
            ulonglong2 a = *(const ulonglong2*)(h2s + r * 128 + k4);
            ffma2(acc0[r], a.x, w0.x);
            ffma2(acc0[r], a.y, w0.y);
            ffma2(acc1[r], a.x, w1.x);
            ffma2(acc1[r], a.y, w1.y);
        }
    }
#pragma unroll
    for (int r = 0; r < 8; r++) {
        scratch[half * 4096 + r * 512 + t2]       = sum2(acc0[r]);
        scratch[half * 4096 + r * 512 + t2 + 256] = sum2(acc1[r]);
    }
    __syncthreads();

    const int d  = tid & 7;
    const int h0 = tid >> 3;
    const float b3v = b3s[tid];
#pragma unroll
    for (int r = 0; r < 8; r++) {
        float v = scratch[r * 512 + tid] + scratch[4096 + r * 512 + tid] + b3v;
        float f = tanh_f(v) * dxs[r * 8 + d];
        f += __shfl_xor_sync(0xffffffffu, f, 1);
        f += __shfl_xor_sync(0xffffffffu, f, 2);
        f += __shfl_xor_sync(0xffffffffu, f, 4);
        if (d == 0) kout[r * 64 + h0] = f;
    }
}

__device__ __forceinline__ void vf(const float* __restrict__ ysrc, float* __restrict__ kout,
                                   const float* w1k, const float* b1s,
                                   const ulonglong2* w2r, const float* b2s,
                                   const float* w3c, const float* b3s,
                                   const float* dxs,
                                   float* scratch, float* h1, float* h2, int tid) {
    dense_sk<128, 64, ACT_SP>(w1k, b1s, ysrc, scratch, h1, tid);
    __syncthreads();
    dense2_reg(w2r, b2s, h1, scratch, h2, tid);
    __syncthreads();
    l3_sk(h2, w3c, b3s, dxs, scratch, kout, tid);
    __syncthreads();
}

__device__ __forceinline__ void write_out(const float* __restrict__ y,
                                          const float* __restrict__ lws, float lbv,
                                          float* __restrict__ out, int b0, int t, int tid) {
    int w = tid >> 5, l = tid & 31;
    if (w < 8) {
        float p = y[w * 64 + l] * lws[l] + y[w * 64 + 32 + l] * lws[32 + l];
#pragma unroll
        for (int s = 16; s > 0; s >>= 1) p += __shfl_xor_sync(0xffffffffu, p, s);
        if (l == 0) {
            float z = p + lbv;
            out[(b0 + w) * 64 + t] = __fdividef(1.f, 1.f + __expf(-z));
        }
    }
}

__global__ void __launch_bounds__(NT, 1)
cde_kernel(const float* __restrict__ ts, const float* __restrict__ xs,
           const float* __restrict__ ib1, const float* __restrict__ ib2,
           const float* __restrict__ ib3,
           const float* __restrict__ vb1, const float* __restrict__ vb2,
           const float* __restrict__ vb3,
           const float* __restrict__ lw, const float* __restrict__ lb,
           float* __restrict__ out) {
    extern __shared__ float sm[];
    const int tid = threadIdx.x;
    const int b0 = blockIdx.x * BT;

    float* w1k = sm + OFF_W1;
    float* w3c = sm + OFF_W3C;
    float* b1s = sm + OFF_B1;
    float* b2s = sm + OFF_B2;
    float* b3s = sm + OFF_B3;
    float* lws = sm + OFF_LW;
    float* dxs = sm + OFF_DX;
    float* ybuf = sm + OFF_Y;
    float* yts = sm + OFF_YT;
    float* h1 = sm + OFF_H1;
    float* h2 = sm + OFF_H2;
    float* ksb = sm + OFF_K;
    float* scratch = sm + OFF_SC;

    // ---------- stage weights + misc into smem ----------
    for (int i = tid; i < 8192; i += NT) w1k[i] = g_vw1k[i];
    // vw3 cols 256..511 -> smem cache: w3c[kq*1024 + j] = g_vw3q[kq*2048 + 1024 + j]
    for (int i = tid; i < 32768; i += NT)
        w3c[i] = g_vw3q[(i >> 10) * 2048 + 1024 + (i & 1023)];
    for (int i = tid; i < 128; i += NT) { b1s[i] = vb1[i]; b2s[i] = vb2[i]; }
    for (int i = tid; i < 512; i += NT) b3s[i] = vb3[i];
    if (tid < 64) lws[tid] = lw[tid];
    if (tid < 64) {
        int r = tid >> 3, d = tid & 7;
        dxs[tid] = xs[(b0 + r) * 512 + d];         // X(t0)
    }
    const float lbv = lb[0];

    // ---------- register-resident vw2 slice (survives whole kernel) ----------
    ulonglong2 w2r[16];
    {
        const int half = tid >> 8;
        const int c = (tid & 255) & 127;
#pragma unroll
        for (int q = 0; q < 16; q++)
            w2r[q] = *(const ulonglong2*)(g_vw2k + (half * 16 + q) * 512 + c * 4);
    }
    __syncthreads();

    // ---------- initial MLP (weights straight from global k-major) ----------
    dense_sk<128, 8, ACT_RELU>(g_iw1k, ib1, dxs, scratch, h1, tid);
    __syncthreads();
    dense_sk<128, 128, ACT_RELU>(g_iw2k, ib2, h1, scratch, h2, tid);
    __syncthreads();
    dense_sk<64, 128, ACT_ID>(g_iw3k, ib3, h2, scratch, ybuf, tid);
    __syncthreads();

    write_out(ybuf, lws, lbv, out, b0, 0, tid);
    __syncthreads();

    // Tsit5 coefficients
    const float A21 = 0.161f;
    const float A31 = -0.008480655492356989f, A32 = 0.335480655492357f;
    const float A41 = 2.8971530571054935f, A42 = -6.359448489975075f, A43 = 4.3622954328695815f;
    const float A51 = 5.325864828439257f, A52 = -11.748883564062828f, A53 = 7.4955393428898365f, A54 = -0.09249506636175525f;
    const float A61 = 5.86145544294642f, A62 = -12.92096931784711f, A63 = 8.159367898576159f, A64 = -0.071584973281401f, A65 = -0.028269050394068383f;
    const float B1 = 0.09646076681806523f, B2 = 0.01f, B3 = 0.4798896504144996f;
    const float B4 = 1.379008574103742f, B5 = -3.290069515436081f, B6 = 2.324710524099774f;

    float* k1 = ksb;
    float* k2 = ksb + 512;
    float* k3 = ksb + 1024;
    float* k4 = ksb + 1536;
    float* k5 = ksb + 2048;
    float* k6 = ksb + 2560;

    for (int t = 0; t < 63; t++) {
        const float dt = ts[t + 1] - ts[t];
        if (tid < 64) {
            int r = tid >> 3, d = tid & 7;
            int ix = (b0 + r) * 512 + t * 8 + d;
            dxs[tid] = (xs[ix + 8] - xs[ix]) / dt;
        }
        __syncthreads();

        // stage 1
        vf(ybuf, k1, w1k, b1s, w2r, b2s, w3c, b3s, dxs, scratch, h1, h2, tid);
        {
            int e = tid;
            yts[e] = ybuf[e] + dt * (A21 * k1[e]);
        }
        __syncthreads();
        // stage 2
        vf(yts, k2, w1k, b1s, w2r, b2s, w3c, b3s, dxs, scratch, h1, h2, tid);
        {
            int e = tid;
            yts[e] = ybuf[e] + dt * (A31 * k1[e] + A32 * k2[e]);
        }
        __syncthreads();
        // stage 3
        vf(yts, k3, w1k, b1s, w2r, b2s, w3c, b3s, dxs, scratch, h1, h2, tid);
        {
            int e = tid;
            yts[e] = ybuf[e] + dt * (A41 * k1[e] + A42 * k2[e] + A43 * k3[e]);
        }
        __syncthreads();
        // stage 4
        vf(yts, k4, w1k, b1s, w2r, b2s, w3c, b3s, dxs, scratch, h1, h2, tid);
        {
            int e = tid;
            yts[e] = ybuf[e] + dt * (A51 * k1[e] + A52 * k2[e] + A53 * k3[e] + A54 * k4[e]);
        }
        __syncthreads();
        // stage 5
        vf(yts, k5, w1k, b1s, w2r, b2s, w3c, b3s, dxs, scratch, h1, h2, tid);
        {
            int e = tid;
            yts[e] = ybuf[e] + dt * (A61 * k1[e] + A62 * k2[e] + A63 * k3[e] + A64 * k4[e] + A65 * k5[e]);
        }
        __syncthreads();
        // stage 6
        vf(yts, k6, w1k, b1s, w2r, b2s, w3c, b3s, dxs, scratch, h1, h2, tid);
        {
            int e = tid;
            ybuf[e] = ybuf[e] + dt * (B1 * k1[e] + B2 * k2[e] + B3 * k3[e]
                                    + B4 * k4[e] + B5 * k5[e] + B6 * k6[e]);
        }
        __syncthreads();
        write_out(ybuf, lws, lbv, out, b0, t + 1, tid);
        __syncthreads();
    }
}

extern "C" void kernel_launch(void* const* d_in, const int* in_sizes, int n_in,
                              void* d_out, int out_size) {
    const float* ts  = (const float*)d_in[0];
    const float* xs  = (const float*)d_in[1];
    const float* iw1 = (const float*)d_in[2];
    const float* ib1 = (const float*)d_in[3];
    const float* iw2 = (const float*)d_in[4];
    const float* ib2 = (const float*)d_in[5];
    const float* iw3 = (const float*)d_in[6];
    const float* ib3 = (const float*)d_in[7];
    const float* vw1 = (const float*)d_in[8];
    const float* vb1 = (const float*)d_in[9];
    const float* vw2 = (const float*)d_in[10];
    const float* vb2 = (const float*)d_in[11];
    const float* vw3 = (const float*)d_in[12];
    const float* vb3 = (const float*)d_in[13];
    const float* lw  = (const float*)d_in[14];
    const float* lb  = (const float*)d_in[15];
    float* out = (float*)d_out;

    float *p_vw3q, *p_vw1k, *p_vw2k, *p_iw1k, *p_iw2k, *p_iw3k;
    cudaGetSymbolAddress((void**)&p_vw3q, g_vw3q);
    cudaGetSymbolAddress((void**)&p_vw1k, g_vw1k);
    cudaGetSymbolAddress((void**)&p_vw2k, g_vw2k);
    cudaGetSymbolAddress((void**)&p_iw1k, g_iw1k);
    cudaGetSymbolAddress((void**)&p_iw2k, g_iw2k);
    cudaGetSymbolAddress((void**)&p_iw3k, g_iw3k);

    prep_kmajor<<<(512 * 128 + 255) / 256, 256>>>(p_vw3q, vw3, 512, 128);
    prep_kmajor<<<(128 * 64 + 255) / 256, 256>>>(p_vw1k, vw1, 128, 64);
    prep_kmajor<<<(128 * 128 + 255) / 256, 256>>>(p_vw2k, vw2, 128, 128);
    prep_kmajor<<<(128 * 8 + 255) / 256, 256>>>(p_iw1k, iw1, 128, 8);
    prep_kmajor<<<(128 * 128 + 255) / 256, 256>>>(p_iw2k, iw2, 128, 128);
    prep_kmajor<<<(64 * 128 + 255) / 256, 256>>>(p_iw3k, iw3, 64, 128);

    cudaFuncSetAttribute(cde_kernel, cudaFuncAttributeMaxDynamicSharedMemorySize, SMEM_BYTES);
    cde_kernel<<<128, NT, SMEM_BYTES>>>(ts, xs, ib1, ib2, ib3,
                                        vb1, vb2, vb3, lw, lb, out);
}